// round 6
// baseline (speedup 1.0000x reference)
#include <cuda_runtime.h>
#include <cstdint>
#include <math_constants.h>

#define NI    1024
#define NC    201
#define TT    100
#define ROW   (NC * TT)           // 20100
#define NPAIR (NI * NC)           // 205824
#define GRID1 (2 * NI)            // 2048: even=lab role, odd=softplus role
#define GRID2 256                 // dot kernel

// -------- scratch (no allocations; zero at module load) --------
__device__ double         g_acc;            // running total (reset by k_dot tail)
__device__ float          g_sp[NPAIR];      // per-(n,c) softplus sums
__device__ unsigned char  g_wm[NPAIR];      // weight mask bytes
__device__ unsigned char  g_isbg[NI];
__device__ float          g_bgG[NI * 3];    // bg gather partials [rare, common, base]
__device__ int            g_done1;          // K1 completion counter
__device__ int            g_done2;          // k_dot completion counter

// ======================= threefry2x32 (JAX-exact) =======================
__host__ __device__ constexpr uint32_t rotl32(uint32_t x, int r) {
    return (x << r) | (x >> (32 - r));
}
struct TF2 { uint32_t a, b; };

__host__ __device__ constexpr TF2 tf2x32(uint32_t k0, uint32_t k1,
                                         uint32_t x0, uint32_t x1) {
    uint32_t ks2 = k0 ^ k1 ^ 0x1BD11BDAu;
    uint32_t kk[3] = {k0, k1, ks2};
    const int R0[4] = {13, 15, 26, 6};
    const int R1[4] = {17, 29, 16, 24};
    uint32_t v0 = x0 + k0, v1 = x1 + k1;
    for (int i = 0; i < 5; i++) {
        for (int j = 0; j < 4; j++) {
            int r = (i % 2 == 0) ? R0[j] : R1[j];
            v0 += v1; v1 = rotl32(v1, r); v1 ^= v0;
        }
        v0 += kk[(i + 1) % 3];
        v1 += kk[(i + 2) % 3] + (uint32_t)(i + 1);
    }
    return TF2{v0, v1};
}

constexpr TF2      S98 = tf2x32(0u, 42u, 98u, 198u);
constexpr TF2      S99 = tf2x32(0u, 42u, 99u, 199u);
constexpr uint32_t KLA = S98.b, KLB = S99.b;
constexpr TF2      SP0 = tf2x32(KLA, KLB, 0u, 2u);
constexpr TF2      SP1 = tf2x32(KLA, KLB, 1u, 3u);
constexpr uint32_t K1A = SP0.a, K1B = SP1.a;
constexpr uint32_t K2A = SP0.b, K2B = SP1.b;

__device__ __forceinline__ float tf_uniform(uint32_t ka, uint32_t kb, int n) {
    TF2 r = (n < 512) ? tf2x32(ka, kb, (uint32_t)n,         (uint32_t)(n + 512))
                      : tf2x32(ka, kb, (uint32_t)(n - 512), (uint32_t)n);
    uint32_t bits = (n < 512) ? r.a : r.b;
    return __uint_as_float((bits >> 9) | 0x3f800000u) - 1.0f;
}

// ======================= K1: both streams, interleaved =====================
__global__ __launch_bounds__(256) void k_main(const float* __restrict__ cls,
                                              const float* __restrict__ labels) {
    __shared__ union {
        struct { float best[8][100]; int bi[8][100]; } pa;   // lab role
        float part[NC * 25];                                  // sp role (20.1KB)
        struct { int idx[NI]; float u1[NI]; float u2[NI];
                 unsigned char sel[NI]; } tl;                 // tail (13.3KB)
    } u;
    __shared__ int    sLab[TT];
    __shared__ double sGat[NC];
    __shared__ float  sG3[3];
    __shared__ double sRed[8];
    __shared__ int    sLast, sCnt;

    int bid  = blockIdx.x;
    int n    = bid >> 1;
    int role = bid & 1;                 // 0 = labels/argmax, 1 = softplus sums
    int tid  = threadIdx.x;
    int w    = tid >> 5;
    int lane = tid & 31;

    const float* crow = cls + (size_t)n * ROW;

    if (role == 1) {
        // ---------------- softplus role: per-(n,c) sums ----------------
        if (lane < 25) {
            #pragma unroll 4
            for (int c = w; c < NC; c += 8) {
                float4 x = __ldg((const float4*)(crow + c * TT) + lane);
                float m = fmaxf(x.x, 0.f) + fmaxf(x.y, 0.f)
                        + fmaxf(x.z, 0.f) + fmaxf(x.w, 0.f);
                float l = __log2f(1.f + __expf(-fabsf(x.x)))
                        + __log2f(1.f + __expf(-fabsf(x.y)))
                        + __log2f(1.f + __expf(-fabsf(x.z)))
                        + __log2f(1.f + __expf(-fabsf(x.w)));
                u.part[c * 25 + lane] = m + 0.69314718056f * l;
            }
        }
        __syncthreads();
        if (tid < NC) {
            float s = 0.f;
            #pragma unroll
            for (int i = 0; i < 25; i++) s += u.part[tid * 25 + i];
            g_sp[n * NC + tid] = s;
        }
    } else {
        // ---------------- label role: argmax + wm + gather dots ----------------
        const float* lrow = labels + (size_t)n * ROW;
        if (tid < NC) sGat[tid] = 0.0;
        if (tid < 3)  sG3[tid]  = 0.f;

        if (lane < 25) {
            float b0 = -CUDART_INF_F, b1 = -CUDART_INF_F,
                  b2 = -CUDART_INF_F, b3 = -CUDART_INF_F;
            int i0 = 0, i1 = 0, i2 = 0, i3 = 0;
            #pragma unroll 4
            for (int c = w; c < NC; c += 8) {
                float4 v = __ldg((const float4*)(lrow + c * TT) + lane);
                if (v.x > b0) { b0 = v.x; i0 = c; }
                if (v.y > b1) { b1 = v.y; i1 = c; }
                if (v.z > b2) { b2 = v.z; i2 = c; }
                if (v.w > b3) { b3 = v.w; i3 = c; }
            }
            int t = lane * 4;
            u.pa.best[w][t + 0] = b0; u.pa.bi[w][t + 0] = i0;
            u.pa.best[w][t + 1] = b1; u.pa.bi[w][t + 1] = i1;
            u.pa.best[w][t + 2] = b2; u.pa.bi[w][t + 2] = i2;
            u.pa.best[w][t + 3] = b3; u.pa.bi[w][t + 3] = i3;
        }
        __syncthreads();

        // combine partials; first-max tie-break (lower c wins)
        if (tid < TT) {
            float b = u.pa.best[0][tid]; int bi = u.pa.bi[0][tid];
            #pragma unroll
            for (int ww = 1; ww < 8; ww++) {
                float v = u.pa.best[ww][tid]; int c = u.pa.bi[ww][tid];
                if (v > b || (v == b && c < bi)) { b = v; bi = c; }
            }
            sLab[tid] = bi;
        }
        __syncthreads();

        int  lab99 = sLab[TT - 1];
        bool isbg  = (lab99 == NC - 1);
        if (tid == 0) g_isbg[n] = (unsigned char)isbg;

        // gather: sum_t x[n, lab[t], t] binned per class
        if (tid < TT) {
            int lb = sLab[tid];
            atomicAdd(&sGat[lb], (double)__ldg(crow + (size_t)lb * TT + tid));
        }
        __syncthreads();

        float neg = 0.f;
        if (tid < NC) {
            float g = (float)sGat[tid];
            if (!isbg) {
                float x99 = __ldg(crow + (size_t)tid * TT + 99);
                float sg  = 1.f / (1.f + __expf(-x99));
                bool wm = (tid == lab99) || (sg >= 0.3f);
                g_wm[n * NC + tid] = (unsigned char)wm;
                if (wm) neg = g;
            } else if (g != 0.f) {
                int r = (tid >= 150) ? 2 : (tid >= 50 ? 1 : 0);
                atomicAdd(&sG3[r], g);
            }
        }

        #pragma unroll
        for (int o = 16; o; o >>= 1) neg += __shfl_xor_sync(0xffffffffu, neg, o);
        if (lane == 0) sRed[w] = (double)neg;
        __syncthreads();
        if (tid == 0 && !isbg) {
            double s = 0.0;
            #pragma unroll
            for (int i = 0; i < 8; i++) s += sRed[i];
            atomicAdd(&g_acc, -s);
        }
        if (isbg && tid < 3) g_bgG[n * 3 + tid] = sG3[tid];
    }

    // ---------------- completion; last block runs bg selection ----------------
    __syncthreads();
    if (tid == 0) {
        __threadfence();
        int old = atomicAdd(&g_done1, 1);
        sLast = (old == GRID1 - 1);
    }
    __syncthreads();
    if (!sLast) return;
    __threadfence();

    if (tid == 0) sCnt = 0;
    __syncthreads();

    for (int i = tid; i < NI; i += 256) {
        if (g_isbg[i]) {
            int p = atomicAdd(&sCnt, 1);
            u.tl.idx[p] = i;
            u.tl.u1[p]  = tf_uniform(K1A, K1B, i);
            u.tl.u2[p]  = tf_uniform(K2A, K2B, i);
        }
    }
    __syncthreads();

    int nbg = sCnt;
    int kr  = nbg / 100;            // int(n_bg * 0.01)
    int kc  = nbg / 10;             // int(n_bg * 0.10)

    // stable-argsort ranks among bg rows
    for (int i = tid; i < nbg; i += 256) {
        float u1 = u.tl.u1[i], u2 = u.tl.u2[i];
        int   m  = u.tl.idx[i];
        int r1 = 0, r2 = 0;
        for (int j = 0; j < nbg; j++) {
            float a = u.tl.u1[j], b = u.tl.u2[j];
            int  mj = u.tl.idx[j];
            r1 += (a < u1) || (a == u1 && mj < m);
            r2 += (b < u2) || (b == u2 && mj < m);
        }
        u.tl.sel[i] = (unsigned char)((r1 < kr ? 2u : 0u) | (r2 < kc ? 4u : 0u));
    }
    __syncthreads();

    // bg gather dot + bg wm bytes
    double a = 0.0;
    for (int i = tid; i < nbg; i += 256) {
        const float* G = &g_bgG[u.tl.idx[i] * 3];
        unsigned f = u.tl.sel[i];
        a += (double)G[2];
        if (f & 2u) a += (double)G[0];
        if (f & 4u) a += (double)G[1];
    }
    for (int q = tid; q < nbg * NC; q += 256) {
        int i = q / NC;
        int c = q - i * NC;
        unsigned f = u.tl.sel[i];
        bool wm = (c >= 150) || ((f & 2u) && c < 50) ||
                  ((f & 4u) && c >= 50 && c < 150);
        g_wm[u.tl.idx[i] * NC + c] = (unsigned char)wm;
    }

    #pragma unroll
    for (int o = 16; o; o >>= 1) a += __shfl_xor_sync(0xffffffffu, a, o);
    if (lane == 0) sRed[w] = a;
    __syncthreads();
    if (tid == 0) {
        double s = 0.0;
        #pragma unroll
        for (int i = 0; i < 8; i++) s += sRed[i];
        atomicAdd(&g_acc, -s);
        g_done1 = 0;                // reset for next graph replay
    }
}

// ======================= K2: wm . sp dot + finalize ========================
__global__ __launch_bounds__(256) void k_dot(float* __restrict__ out) {
    __shared__ double sRed[8];
    __shared__ int    sLast;

    int tid  = threadIdx.x;
    int w    = tid >> 5;
    int lane = tid & 31;
    int stride = GRID2 * 256;

    double acc = 0.0;
    for (int p = blockIdx.x * 256 + tid; p < NPAIR; p += stride)
        if (g_wm[p]) acc += (double)g_sp[p];

    #pragma unroll
    for (int o = 16; o; o >>= 1) acc += __shfl_xor_sync(0xffffffffu, acc, o);
    if (lane == 0) sRed[w] = acc;
    __syncthreads();
    if (tid == 0) {
        double s = 0.0;
        #pragma unroll
        for (int i = 0; i < 8; i++) s += sRed[i];
        atomicAdd(&g_acc, s);
        __threadfence();
        int old = atomicAdd(&g_done2, 1);
        sLast = (old == GRID2 - 1);
    }
    __syncthreads();
    if (sLast && tid == 0) {
        double tot = atomicAdd(&g_acc, 0.0);      // all contributions visible
        out[0] = (float)(tot * (1.0 / ((double)NI * (double)TT)));
        g_acc   = 0.0;                            // reset for next graph replay
        g_done2 = 0;
    }
}

// ======================= launcher ==========================================
extern "C" void kernel_launch(void* const* d_in, const int* in_sizes, int n_in,
                              void* d_out, int out_size) {
    const float* cls    = (const float*)d_in[0];   // [1024,201,100]
    const float* labels = (const float*)d_in[1];   // [1024,201,100]
    float* out = (float*)d_out;

    k_main<<<GRID1, 256>>>(cls, labels);
    k_dot <<<GRID2, 256>>>(out);
}